// round 4
// baseline (speedup 1.0000x reference)
#include <cuda_runtime.h>
#include <cuda_bf16.h>
#include <math.h>
#include <stdint.h>

#define MR 2
#define NE 8
#define CD 1024
#define DD 256
#define BB 32
#define SS 512
#define STAGES 3
#define STAGE_BYTES 32768   // Ah 8K | Al 8K | Bh 8K | Bl 8K
#define SMEM_TOTAL (STAGES * STAGE_BYTES)

typedef __nv_bfloat16 bf16;

// ---------------- static device scratch (no allocs) ----------------
__device__ bf16 g_x_h[(size_t)BB * SS * CD];
__device__ bf16 g_x_l[(size_t)BB * SS * CD];
__device__ bf16 g_z_h[(size_t)MR * BB * SS * DD];
__device__ bf16 g_z_l[(size_t)MR * BB * SS * DD];
__device__ bf16 g_dwT_h[(size_t)MR * NE * DD * CD];
__device__ bf16 g_dwT_l[(size_t)MR * NE * DD * CD];
__device__ bf16 g_uwT_h[(size_t)MR * NE * CD * DD];
__device__ bf16 g_uwT_l[(size_t)MR * NE * CD * DD];

// ---------------- ptx helpers ----------------
__device__ __forceinline__ uint32_t smem_u32(const void* p) {
    uint32_t a;
    asm("{ .reg .u64 t; cvta.to.shared.u64 t, %1; cvt.u32.u64 %0, t; }" : "=r"(a) : "l"(p));
    return a;
}
#define CP16(dst, src) \
    asm volatile("cp.async.cg.shared.global [%0], [%1], 16;" :: "r"(dst), "l"(src))
#define CP_COMMIT() asm volatile("cp.async.commit_group;")
#define CP_WAIT1()  asm volatile("cp.async.wait_group 1;")
#define CP_WAIT0()  asm volatile("cp.async.wait_group 0;")

#define LDSM4(r, a) \
    asm volatile("ldmatrix.sync.aligned.m8n8.x4.shared.b16 {%0,%1,%2,%3}, [%4];" \
        : "=r"((r)[0]), "=r"((r)[1]), "=r"((r)[2]), "=r"((r)[3]) : "r"(a))

#define MMA(d, a, b0, b1) \
    asm volatile("mma.sync.aligned.m16n8k16.row.col.f32.bf16.bf16.f32 " \
        "{%0,%1,%2,%3},{%4,%5,%6,%7},{%8,%9},{%0,%1,%2,%3};" \
        : "+f"((d)[0]), "+f"((d)[1]), "+f"((d)[2]), "+f"((d)[3]) \
        : "r"((a)[0]), "r"((a)[1]), "r"((a)[2]), "r"((a)[3]), "r"(b0), "r"(b1))

// XOR swizzle: 128 rows x 32 bf16 (64B rows, 4 x 16B chunks); conflict-free ldmatrix
__device__ __forceinline__ uint32_t swz(uint32_t row, uint32_t chunk) {
    return row * 64u + ((chunk ^ ((row >> 1) & 3u)) << 4);
}

// ---------------- stage loader: 8x cp.async(16B) per thread ----------------
__device__ __forceinline__ void stage_load(uint32_t sbase,
                                           const bf16* __restrict__ Ah,
                                           const bf16* __restrict__ Al, int lda,
                                           const bf16* __restrict__ Bh,
                                           const bf16* __restrict__ Bl, int ldb,
                                           int kc, int tid) {
    #pragma unroll
    for (int i = 0; i < 2; i++) {
        int q = tid + (i << 8);        // 512 chunks: 128 rows x 4 chunks
        int r = q >> 2, c = q & 3;
        uint32_t so = swz(r, c);
        size_t ao = (size_t)r * lda + kc + c * 8;
        size_t bo = (size_t)r * ldb + kc + c * 8;
        CP16(sbase + so,          Ah + ao);
        CP16(sbase + so + 8192,   Al + ao);
        CP16(sbase + so + 16384,  Bh + bo);
        CP16(sbase + so + 24576,  Bl + bo);
    }
}

// ---------------- GEMM mainloop: acc[4][4][4] = split-bf16(A[128xK] @ B^T[128xK]) --
// Multistage (1 sync/iter); term-major MMA order breaks the acc RAW chain.
__device__ __forceinline__ void gemm_main(uint32_t smem_b,
                                          const bf16* __restrict__ Ah,
                                          const bf16* __restrict__ Al, int lda,
                                          const bf16* __restrict__ Bh,
                                          const bf16* __restrict__ Bl, int ldb,
                                          int nk, float acc[4][4][4], int tid) {
    const int lane = tid & 31, warp = tid >> 5;
    const int wm = (warp & 1) * 64, wn = (warp >> 1) * 32;

    // prologue: stages 0,1
    stage_load(smem_b, Ah, Al, lda, Bh, Bl, ldb, 0, tid);  CP_COMMIT();
    stage_load(smem_b + STAGE_BYTES, Ah, Al, lda, Bh, Bl, ldb, 32, tid);  CP_COMMIT();

    const int r15 = lane & 15, chi = lane >> 4;

    for (int k = 0; k < nk; k++) {
        if (k + 2 < nk) { CP_WAIT1(); } else { CP_WAIT0(); }
        __syncthreads();   // stage k ready for all; all done computing stage k-1
        if (k + 2 < nk) {
            stage_load(smem_b + ((k + 2) % STAGES) * STAGE_BYTES,
                       Ah, Al, lda, Bh, Bl, ldb, (k + 2) * 32, tid);
            CP_COMMIT();
        }
        uint32_t sb = smem_b + (k % STAGES) * STAGE_BYTES;
        #pragma unroll
        for (int ks = 0; ks < 2; ks++) {
            const uint32_t ch = ks * 2 + chi;
            uint32_t bh[2][4], bl[2][4], ah[4][4], al[4][4];
            #pragma unroll
            for (int bt = 0; bt < 2; bt++) {
                uint32_t ab = sb + 16384 + swz(wn + bt * 16 + r15, ch);
                LDSM4(bh[bt], ab);
                LDSM4(bl[bt], ab + 8192);
            }
            #pragma unroll
            for (int mt = 0; mt < 4; mt++) {
                uint32_t aa = sb + swz(wm + mt * 16 + r15, ch);
                LDSM4(ah[mt], aa);
                LDSM4(al[mt], aa + 8192);
            }
            // term-major passes: acc reuse distance = 16 MMAs (hides HMMA latency)
            #pragma unroll
            for (int mt = 0; mt < 4; mt++)
                #pragma unroll
                for (int nt = 0; nt < 4; nt++) {
                    const int b2 = nt >> 1, s = nt & 1;
                    MMA(acc[mt][nt], ah[mt], bh[b2][s], bh[b2][2 + s]);
                }
            #pragma unroll
            for (int mt = 0; mt < 4; mt++)
                #pragma unroll
                for (int nt = 0; nt < 4; nt++) {
                    const int b2 = nt >> 1, s = nt & 1;
                    MMA(acc[mt][nt], ah[mt], bl[b2][s], bl[b2][2 + s]);
                }
            #pragma unroll
            for (int mt = 0; mt < 4; mt++)
                #pragma unroll
                for (int nt = 0; nt < 4; nt++) {
                    const int b2 = nt >> 1, s = nt & 1;
                    MMA(acc[mt][nt], al[mt], bh[b2][s], bh[b2][2 + s]);
                }
        }
        // no trailing sync: next iteration's top sync protects stage overwrite
    }
}

// ---------------- down: z = silu(x @ dw + db), z stored bf16 hi/lo -----------
__global__ void __launch_bounds__(256)
down_mma(const int* __restrict__ eidx, const float* __restrict__ db) {
    extern __shared__ char smem[];
    uint32_t smem_b = smem_u32(smem);
    const int tid = threadIdx.x, lane = tid & 31, warp = tid >> 5;
    const int wm = (warp & 1) * 64, wn = (warp >> 1) * 32;
    const int stile = blockIdx.x >> 1, ntile = blockIdx.x & 1;
    const int b = blockIdx.y, m = blockIdx.z;
    const int e = eidx[m * BB + b];

    const bf16* Ah = g_x_h + ((size_t)b * SS + stile * 128) * CD;
    const bf16* Al = g_x_l + ((size_t)b * SS + stile * 128) * CD;
    const bf16* Bh = g_dwT_h + (size_t)(m * NE + e) * DD * CD + (size_t)(ntile * 128) * CD;
    const bf16* Bl = g_dwT_l + (size_t)(m * NE + e) * DD * CD + (size_t)(ntile * 128) * CD;

    float acc[4][4][4];
    #pragma unroll
    for (int i = 0; i < 4; i++)
        #pragma unroll
        for (int j = 0; j < 4; j++)
            #pragma unroll
            for (int q = 0; q < 4; q++) acc[i][j][q] = 0.f;

    gemm_main(smem_b, Ah, Al, CD, Bh, Bl, CD, CD / 32, acc, tid);

    const float* bias = db + (size_t)(m * NE + e) * DD;
    const size_t zrow0 = ((size_t)(m * BB + b) * SS + stile * 128);
    const int r0 = lane >> 2, cp = 2 * (lane & 3);

    #pragma unroll
    for (int mt = 0; mt < 4; mt++) {
        #pragma unroll
        for (int nt = 0; nt < 4; nt++) {
            const int col = ntile * 128 + wn + nt * 8 + cp;
            const float2 bv = *reinterpret_cast<const float2*>(bias + col);
            #pragma unroll
            for (int h = 0; h < 2; h++) {   // two row halves (r0, r0+8)
                float v0 = acc[mt][nt][2 * h + 0] + bv.x;
                float v1 = acc[mt][nt][2 * h + 1] + bv.y;
                v0 = v0 / (1.f + __expf(-v0));
                v1 = v1 / (1.f + __expf(-v1));
                bf16 h0 = __float2bfloat16(v0), h1 = __float2bfloat16(v1);
                bf16 l0 = __float2bfloat16(v0 - __bfloat162float(h0));
                bf16 l1 = __float2bfloat16(v1 - __bfloat162float(h1));
                const size_t off = (zrow0 + wm + mt * 16 + r0 + h * 8) * DD + col;
                __nv_bfloat162 hp; hp.x = h0; hp.y = h1;
                __nv_bfloat162 lp; lp.x = l0; lp.y = l1;
                *reinterpret_cast<__nv_bfloat162*>(g_z_h + off) = hp;
                *reinterpret_cast<__nv_bfloat162*>(g_z_l + off) = lp;
            }
        }
    }
}

// ---------------- up: out = z @ uw (fp32 out) --------------------------------
__global__ void __launch_bounds__(256)
up_mma(const int* __restrict__ eidx, float* __restrict__ out) {
    extern __shared__ char smem[];
    uint32_t smem_b = smem_u32(smem);
    const int tid = threadIdx.x, lane = tid & 31, warp = tid >> 5;
    const int wm = (warp & 1) * 64, wn = (warp >> 1) * 32;
    const int stile = blockIdx.x & 3, ctile = blockIdx.x >> 2;
    const int b = blockIdx.y, m = blockIdx.z;
    const int e = eidx[m * BB + b];

    const bf16* Ah = g_z_h + ((size_t)(m * BB + b) * SS + stile * 128) * DD;
    const bf16* Al = g_z_l + ((size_t)(m * BB + b) * SS + stile * 128) * DD;
    const bf16* Bh = g_uwT_h + (size_t)(m * NE + e) * CD * DD + (size_t)(ctile * 128) * DD;
    const bf16* Bl = g_uwT_l + (size_t)(m * NE + e) * CD * DD + (size_t)(ctile * 128) * DD;

    float acc[4][4][4];
    #pragma unroll
    for (int i = 0; i < 4; i++)
        #pragma unroll
        for (int j = 0; j < 4; j++)
            #pragma unroll
            for (int q = 0; q < 4; q++) acc[i][j][q] = 0.f;

    gemm_main(smem_b, Ah, Al, DD, Bh, Bl, DD, DD / 32, acc, tid);

    const size_t orow0 = ((size_t)(m * BB + b) * SS + stile * 128);
    const int r0 = lane >> 2, cp = 2 * (lane & 3);

    #pragma unroll
    for (int mt = 0; mt < 4; mt++) {
        #pragma unroll
        for (int nt = 0; nt < 4; nt++) {
            const int col = ctile * 128 + wn + nt * 8 + cp;
            #pragma unroll
            for (int h = 0; h < 2; h++) {
                const size_t off = (orow0 + wm + mt * 16 + r0 + h * 8) * CD + col;
                *reinterpret_cast<float2*>(out + off) =
                    make_float2(acc[mt][nt][2 * h + 0], acc[mt][nt][2 * h + 1]);
            }
        }
    }
}

// ---------------- prep: split x fp32 -> bf16 hi/lo ---------------------------
__global__ void __launch_bounds__(256)
x_split(const float* __restrict__ x) {
    size_t i = (size_t)blockIdx.x * 256 + threadIdx.x;   // one float4 each
    float4 v = reinterpret_cast<const float4*>(x)[i];
    float f[4] = {v.x, v.y, v.z, v.w};
    __nv_bfloat162 hp[2], lp[2];
    #pragma unroll
    for (int j = 0; j < 2; j++) {
        bf16 h0 = __float2bfloat16(f[2 * j]), h1 = __float2bfloat16(f[2 * j + 1]);
        hp[j].x = h0; hp[j].y = h1;
        lp[j].x = __float2bfloat16(f[2 * j] - __bfloat162float(h0));
        lp[j].y = __float2bfloat16(f[2 * j + 1] - __bfloat162float(h1));
    }
    reinterpret_cast<__nv_bfloat162*>(g_x_h)[i * 2]     = hp[0];
    reinterpret_cast<__nv_bfloat162*>(g_x_h)[i * 2 + 1] = hp[1];
    reinterpret_cast<__nv_bfloat162*>(g_x_l)[i * 2]     = lp[0];
    reinterpret_cast<__nv_bfloat162*>(g_x_l)[i * 2 + 1] = lp[1];
}

// ---------------- prep: transpose [R x Cc] fp32 -> [Cc x R] bf16 hi/lo -------
__global__ void transpose_cvt(const float* __restrict__ in,
                              bf16* __restrict__ oh, bf16* __restrict__ ol,
                              int R, int Cc) {
    __shared__ float t[32][33];
    const size_t mat = blockIdx.z;
    const float* src = in + mat * (size_t)R * Cc;
    bf16* dh = oh + mat * (size_t)R * Cc;
    bf16* dl = ol + mat * (size_t)R * Cc;
    int c0 = blockIdx.x * 32, r0 = blockIdx.y * 32;
    #pragma unroll
    for (int i = threadIdx.y; i < 32; i += 8)
        t[i][threadIdx.x] = src[(size_t)(r0 + i) * Cc + c0 + threadIdx.x];
    __syncthreads();
    #pragma unroll
    for (int i = threadIdx.y; i < 32; i += 8) {
        float v = t[threadIdx.x][i];
        bf16 h = __float2bfloat16(v);
        size_t o = (size_t)(c0 + i) * R + r0 + threadIdx.x;
        dh[o] = h;
        dl[o] = __float2bfloat16(v - __bfloat162float(h));
    }
}

// ---------------- launch ------------------------------------------------------
extern "C" void kernel_launch(void* const* d_in, const int* in_sizes, int n_in,
                              void* d_out, int out_size) {
    const float* x    = (const float*)d_in[0];   // [B,S,C]
    const int*   eidx = (const int*)d_in[1];     // [M,B]
    const float* dw   = (const float*)d_in[2];   // [M,N,C,D]
    const float* db   = (const float*)d_in[3];   // [M,N,D]
    const float* uw   = (const float*)d_in[4];   // [M,N,D,C]
    float*       out  = (float*)d_out;           // [M,B,S,C]

    bf16 *dwt_h, *dwt_l, *uwt_h, *uwt_l;
    cudaGetSymbolAddress((void**)&dwt_h, g_dwT_h);
    cudaGetSymbolAddress((void**)&dwt_l, g_dwT_l);
    cudaGetSymbolAddress((void**)&uwt_h, g_uwT_h);
    cudaGetSymbolAddress((void**)&uwt_l, g_uwT_l);

    cudaFuncSetAttribute(down_mma, cudaFuncAttributeMaxDynamicSharedMemorySize, SMEM_TOTAL);
    cudaFuncSetAttribute(up_mma,   cudaFuncAttributeMaxDynamicSharedMemorySize, SMEM_TOTAL);

    // preps
    x_split<<<(BB * SS * CD / 4) / 256, 256>>>(x);
    transpose_cvt<<<dim3(DD / 32, CD / 32, MR * NE), dim3(32, 8)>>>(dw, dwt_h, dwt_l, CD, DD);
    transpose_cvt<<<dim3(CD / 32, DD / 32, MR * NE), dim3(32, 8)>>>(uw, uwt_h, uwt_l, DD, CD);

    // GEMMs
    down_mma<<<dim3((SS / 128) * (DD / 128), BB, MR), 256, SMEM_TOTAL>>>(eidx, db);
    up_mma<<<dim3((SS / 128) * (CD / 128), BB, MR), 256, SMEM_TOTAL>>>(eidx, out);
}

// round 5
// speedup vs baseline: 1.1041x; 1.1041x over previous
#include <cuda_runtime.h>
#include <cuda_bf16.h>
#include <math.h>
#include <stdint.h>

#define MR 2
#define NE 8
#define CD 1024
#define DD 256
#define BB 32
#define SS 512
#define STAGES 3
#define STAGE_BYTES 32768   // Ah 8K | Al 8K | Bh 8K | Bl 8K
#define SMEM_TOTAL (STAGES * STAGE_BYTES)

typedef __nv_bfloat16 bf16;

// ---------------- static device scratch (combined hi|lo planes) --------------
// layout: each logical row has 2*ld cols: hi plane at [0,ld), lo plane at [ld,2ld)
__device__ bf16 g_x[(size_t)BB * SS * 2 * CD];          // 67 MB
__device__ bf16 g_z[(size_t)MR * BB * SS * 2 * DD];     // 33.5 MB
__device__ bf16 g_dwT[(size_t)MR * NE * DD * 2 * CD];   // 16.8 MB
__device__ bf16 g_uwT[(size_t)MR * NE * CD * 2 * DD];   // 16.8 MB

// ---------------- ptx helpers ----------------
__device__ __forceinline__ uint32_t smem_u32(const void* p) {
    uint32_t a;
    asm("{ .reg .u64 t; cvta.to.shared.u64 t, %1; cvt.u32.u64 %0, t; }" : "=r"(a) : "l"(p));
    return a;
}
#define CP16(dst, src) \
    asm volatile("cp.async.cg.shared.global [%0], [%1], 16;" :: "r"(dst), "l"(src))
#define CP_COMMIT() asm volatile("cp.async.commit_group;")
#define CP_WAIT1()  asm volatile("cp.async.wait_group 1;")
#define CP_WAIT0()  asm volatile("cp.async.wait_group 0;")

#define LDSM4(r, a) \
    asm volatile("ldmatrix.sync.aligned.m8n8.x4.shared.b16 {%0,%1,%2,%3}, [%4];" \
        : "=r"((r)[0]), "=r"((r)[1]), "=r"((r)[2]), "=r"((r)[3]) : "r"(a))

#define MMA(d, a, b0, b1) \
    asm volatile("mma.sync.aligned.m16n8k16.row.col.f32.bf16.bf16.f32 " \
        "{%0,%1,%2,%3},{%4,%5,%6,%7},{%8,%9},{%0,%1,%2,%3};" \
        : "+f"((d)[0]), "+f"((d)[1]), "+f"((d)[2]), "+f"((d)[3]) \
        : "r"((a)[0]), "r"((a)[1]), "r"((a)[2]), "r"((a)[3]), "r"(b0), "r"(b1))

// XOR swizzle: 128 rows x 32 bf16 (64B rows, 4 x 16B chunks); conflict-free ldmatrix
__device__ __forceinline__ uint32_t swz(uint32_t row, uint32_t chunk) {
    return row * 64u + ((chunk ^ ((row >> 1) & 3u)) << 4);
}
// fragment address: stage base + region + swizzled(row, chunk)
__device__ __forceinline__ uint32_t faddr(uint32_t stg, uint32_t region, int row, int ch) {
    return stg + region + (uint32_t)row * 64u +
           ((uint32_t)(ch ^ ((row >> 1) & 3)) << 4);
}

// ---------------- stage loader: 8x cp.async(16B) per thread ----------------
__device__ __forceinline__ void stage_load(uint32_t sbase,
                                           const bf16* __restrict__ A2, int lda,
                                           const bf16* __restrict__ B2, int ldb,
                                           int kc, int tid) {
    #pragma unroll
    for (int i = 0; i < 2; i++) {
        int q = tid + (i << 8);        // 512 chunks: 128 rows x 4 chunks
        int r = q >> 2, c = q & 3;
        uint32_t so = swz(r, c);
        const bf16* pa = A2 + (size_t)r * (2 * lda) + kc + c * 8;
        const bf16* pb = B2 + (size_t)r * (2 * ldb) + kc + c * 8;
        CP16(sbase + so,          pa);
        CP16(sbase + so + 8192,   pa + lda);
        CP16(sbase + so + 16384,  pb);
        CP16(sbase + so + 24576,  pb + ldb);
    }
}

// ---------------- one k16 sub-step: 3 passes with interleaved LDSM prefetch ---
// volatile asm order = issue order: LSU and tensor pipe overlap.
__device__ __forceinline__ void ks_body(float acc[4][4][4],
                                        uint32_t ah[4][4], uint32_t al[4][4],
                                        uint32_t bh[2][4], uint32_t bhn[2][4],
                                        uint32_t bl[2][4],
                                        uint32_t stg, int ch,
                                        uint32_t nstg, int nch,
                                        int wmr, int wnr) {
    // pass1: ah*bh ; prefetch bl (this ks)
    #pragma unroll
    for (int mt = 0; mt < 4; mt++) {
        if (mt == 0) LDSM4(bl[0], faddr(stg, 24576u, wnr,      ch));
        if (mt == 1) LDSM4(bl[1], faddr(stg, 24576u, wnr + 16, ch));
        #pragma unroll
        for (int nt = 0; nt < 4; nt++)
            MMA(acc[mt][nt], ah[mt], bh[nt >> 1][nt & 1], bh[nt >> 1][2 + (nt & 1)]);
    }
    // pass2: ah*bl ; prefetch al (this ks)
    #pragma unroll
    for (int mt = 0; mt < 4; mt++) {
        if (mt == 0) { LDSM4(al[0], faddr(stg, 8192u, wmr,      ch));
                       LDSM4(al[1], faddr(stg, 8192u, wmr + 16, ch)); }
        if (mt == 1)   LDSM4(al[2], faddr(stg, 8192u, wmr + 32, ch));
        if (mt == 2)   LDSM4(al[3], faddr(stg, 8192u, wmr + 48, ch));
        #pragma unroll
        for (int nt = 0; nt < 4; nt++)
            MMA(acc[mt][nt], ah[mt], bl[nt >> 1][nt & 1], bl[nt >> 1][2 + (nt & 1)]);
    }
    // pass3: al*bh ; prefetch next ah (reuse buffer) + next bh (ping-pong)
    #pragma unroll
    for (int mt = 0; mt < 4; mt++) {
        if (mt == 0) { LDSM4(ah[0], faddr(nstg, 0u, wmr,      nch));
                       LDSM4(ah[1], faddr(nstg, 0u, wmr + 16, nch)); }
        if (mt == 1) { LDSM4(ah[2], faddr(nstg, 0u, wmr + 32, nch));
                       LDSM4(ah[3], faddr(nstg, 0u, wmr + 48, nch)); }
        if (mt == 2) { LDSM4(bhn[0], faddr(nstg, 16384u, wnr,      nch));
                       LDSM4(bhn[1], faddr(nstg, 16384u, wnr + 16, nch)); }
        #pragma unroll
        for (int nt = 0; nt < 4; nt++)
            MMA(acc[mt][nt], al[mt], bh[nt >> 1][nt & 1], bh[nt >> 1][2 + (nt & 1)]);
    }
}

// ---------------- GEMM mainloop ------------------------------------------------
__device__ __forceinline__ void gemm_main(uint32_t smem_b,
                                          const bf16* __restrict__ A2, int lda,
                                          const bf16* __restrict__ B2, int ldb,
                                          int nk, float acc[4][4][4], int tid) {
    const int lane = tid & 31, warp = tid >> 5;
    const int wm = (warp & 1) * 64, wn = (warp >> 1) * 32;
    const int r15 = lane & 15, chi = lane >> 4;
    const int wmr = wm + r15, wnr = wn + r15;
    const int cc0 = chi, cc1 = 2 + chi;

    uint32_t ah[4][4], al[4][4], bhA[2][4], bhB[2][4], bl[2][4];

    // prologue: stages 0,1 in flight; preload iter0/ks0 ah+bh fragments
    stage_load(smem_b, A2, lda, B2, ldb, 0, tid);  CP_COMMIT();
    stage_load(smem_b + STAGE_BYTES, A2, lda, B2, ldb, 32, tid);  CP_COMMIT();
    CP_WAIT1();        // G0 complete
    __syncthreads();   // G0 visible to all threads
    LDSM4(ah[0], faddr(smem_b, 0u, wmr,      cc0));
    LDSM4(ah[1], faddr(smem_b, 0u, wmr + 16, cc0));
    LDSM4(ah[2], faddr(smem_b, 0u, wmr + 32, cc0));
    LDSM4(ah[3], faddr(smem_b, 0u, wmr + 48, cc0));
    LDSM4(bhA[0], faddr(smem_b, 16384u, wnr,      cc0));
    LDSM4(bhA[1], faddr(smem_b, 16384u, wnr + 16, cc0));

    for (int k = 0; k < nk; k++) {
        __syncthreads();   // S1: all reads of stage k-1 (prev body) done
        if (k + 2 < nk) {
            stage_load(smem_b + ((k + 2) % STAGES) * STAGE_BYTES,
                       A2, lda, B2, ldb, (k + 2) * 32, tid);
            CP_COMMIT();
            CP_WAIT1();    // G(k+1) complete (pending <= {G(k+2)})
        } else {
            CP_WAIT0();
        }
        __syncthreads();   // S2: stages k and k+1 visible to all threads

        uint32_t stg  = smem_b + (k % STAGES) * STAGE_BYTES;
        uint32_t stgn = smem_b + ((k + 1) % STAGES) * STAGE_BYTES;
        // ks0: chunk cc0, bh in bhA; tail prefetches ks1 frags (bhB)
        ks_body(acc, ah, al, bhA, bhB, bl, stg, cc0, stg, cc1, wmr, wnr);
        // ks1: chunk cc1, bh in bhB; tail prefetches next-iter ks0 frags (bhA)
        ks_body(acc, ah, al, bhB, bhA, bl, stg, cc1, stgn, cc0, wmr, wnr);
    }
}

// ---------------- down: z = silu(x @ dw + db), z stored combined hi|lo --------
__global__ void __launch_bounds__(256, 2)
down_mma(const int* __restrict__ eidx, const float* __restrict__ db) {
    extern __shared__ char smem[];
    uint32_t smem_b = smem_u32(smem);
    const int tid = threadIdx.x, lane = tid & 31, warp = tid >> 5;
    const int wm = (warp & 1) * 64, wn = (warp >> 1) * 32;
    const int stile = blockIdx.x >> 1, ntile = blockIdx.x & 1;
    const int b = blockIdx.y, m = blockIdx.z;
    const int e = eidx[m * BB + b];

    const bf16* A2 = g_x   + ((size_t)b * SS + stile * 128) * (2 * CD);
    const bf16* B2 = g_dwT + ((size_t)(m * NE + e) * DD + ntile * 128) * (2 * CD);

    float acc[4][4][4];
    #pragma unroll
    for (int i = 0; i < 4; i++)
        #pragma unroll
        for (int j = 0; j < 4; j++)
            #pragma unroll
            for (int q = 0; q < 4; q++) acc[i][j][q] = 0.f;

    gemm_main(smem_b, A2, CD, B2, CD, CD / 32, acc, tid);

    const float* bias = db + (size_t)(m * NE + e) * DD;
    const size_t zrow0 = ((size_t)(m * BB + b) * SS + stile * 128);
    const int r0 = lane >> 2, cp = 2 * (lane & 3);

    #pragma unroll
    for (int mt = 0; mt < 4; mt++) {
        #pragma unroll
        for (int nt = 0; nt < 4; nt++) {
            const int col = ntile * 128 + wn + nt * 8 + cp;
            const float2 bv = *reinterpret_cast<const float2*>(bias + col);
            #pragma unroll
            for (int h = 0; h < 2; h++) {   // two row halves (r0, r0+8)
                float v0 = acc[mt][nt][2 * h + 0] + bv.x;
                float v1 = acc[mt][nt][2 * h + 1] + bv.y;
                v0 = v0 / (1.f + __expf(-v0));
                v1 = v1 / (1.f + __expf(-v1));
                bf16 h0 = __float2bfloat16(v0), h1 = __float2bfloat16(v1);
                bf16 l0 = __float2bfloat16(v0 - __bfloat162float(h0));
                bf16 l1 = __float2bfloat16(v1 - __bfloat162float(h1));
                bf16* zb = g_z + (zrow0 + wm + mt * 16 + r0 + h * 8) * (2 * DD) + col;
                __nv_bfloat162 hp; hp.x = h0; hp.y = h1;
                __nv_bfloat162 lp; lp.x = l0; lp.y = l1;
                *reinterpret_cast<__nv_bfloat162*>(zb)      = hp;
                *reinterpret_cast<__nv_bfloat162*>(zb + DD) = lp;
            }
        }
    }
}

// ---------------- up: out = z @ uw (fp32 out) --------------------------------
__global__ void __launch_bounds__(256, 2)
up_mma(const int* __restrict__ eidx, float* __restrict__ out) {
    extern __shared__ char smem[];
    uint32_t smem_b = smem_u32(smem);
    const int tid = threadIdx.x, lane = tid & 31, warp = tid >> 5;
    const int wm = (warp & 1) * 64, wn = (warp >> 1) * 32;
    const int stile = blockIdx.x & 3, ctile = blockIdx.x >> 2;
    const int b = blockIdx.y, m = blockIdx.z;
    const int e = eidx[m * BB + b];

    const bf16* A2 = g_z   + ((size_t)(m * BB + b) * SS + stile * 128) * (2 * DD);
    const bf16* B2 = g_uwT + ((size_t)(m * NE + e) * CD + ctile * 128) * (2 * DD);

    float acc[4][4][4];
    #pragma unroll
    for (int i = 0; i < 4; i++)
        #pragma unroll
        for (int j = 0; j < 4; j++)
            #pragma unroll
            for (int q = 0; q < 4; q++) acc[i][j][q] = 0.f;

    gemm_main(smem_b, A2, DD, B2, DD, DD / 32, acc, tid);

    const size_t orow0 = ((size_t)(m * BB + b) * SS + stile * 128);
    const int r0 = lane >> 2, cp = 2 * (lane & 3);

    #pragma unroll
    for (int mt = 0; mt < 4; mt++) {
        #pragma unroll
        for (int nt = 0; nt < 4; nt++) {
            const int col = ctile * 128 + wn + nt * 8 + cp;
            #pragma unroll
            for (int h = 0; h < 2; h++) {
                const size_t off = (orow0 + wm + mt * 16 + r0 + h * 8) * CD + col;
                *reinterpret_cast<float2*>(out + off) =
                    make_float2(acc[mt][nt][2 * h + 0], acc[mt][nt][2 * h + 1]);
            }
        }
    }
}

// ---------------- prep: split x fp32 -> combined bf16 hi|lo ------------------
__global__ void __launch_bounds__(256)
x_split(const float* __restrict__ x) {
    size_t f = ((size_t)blockIdx.x * 256 + threadIdx.x) * 4;
    size_t row = f >> 10;            // / CD
    int c = (int)(f & (CD - 1));
    float4 v = *reinterpret_cast<const float4*>(x + f);
    float fv[4] = {v.x, v.y, v.z, v.w};
    __nv_bfloat162 hp[2], lp[2];
    #pragma unroll
    for (int j = 0; j < 2; j++) {
        bf16 h0 = __float2bfloat16(fv[2 * j]), h1 = __float2bfloat16(fv[2 * j + 1]);
        hp[j].x = h0; hp[j].y = h1;
        lp[j].x = __float2bfloat16(fv[2 * j] - __bfloat162float(h0));
        lp[j].y = __float2bfloat16(fv[2 * j + 1] - __bfloat162float(h1));
    }
    bf16* base = g_x + row * (2 * CD);
    *reinterpret_cast<uint2*>(base + c) =
        make_uint2(*reinterpret_cast<uint32_t*>(&hp[0]), *reinterpret_cast<uint32_t*>(&hp[1]));
    *reinterpret_cast<uint2*>(base + CD + c) =
        make_uint2(*reinterpret_cast<uint32_t*>(&lp[0]), *reinterpret_cast<uint32_t*>(&lp[1]));
}

// ---------------- prep: transpose [R x Cc] fp32 -> [Cc x 2R] combined bf16 ---
__global__ void transpose_cvt(const float* __restrict__ in,
                              bf16* __restrict__ outc, int R, int Cc) {
    __shared__ float t[32][33];
    const size_t mat = blockIdx.z;
    const float* src = in + mat * (size_t)R * Cc;
    bf16* dst = outc + mat * (size_t)Cc * 2 * R;
    int c0 = blockIdx.x * 32, r0 = blockIdx.y * 32;
    int tx = threadIdx.x;
    #pragma unroll
    for (int i = threadIdx.y; i < 32; i += 8)
        t[i][tx] = src[(size_t)(r0 + i) * Cc + c0 + tx];
    __syncthreads();
    #pragma unroll
    for (int i = threadIdx.y; i < 32; i += 8) {
        float v = t[tx][i];
        bf16 h = __float2bfloat16(v);
        size_t o = (size_t)(c0 + i) * 2 * R + r0 + tx;
        dst[o]     = h;
        dst[o + R] = __float2bfloat16(v - __bfloat162float(h));
    }
}

// ---------------- launch ------------------------------------------------------
extern "C" void kernel_launch(void* const* d_in, const int* in_sizes, int n_in,
                              void* d_out, int out_size) {
    const float* x    = (const float*)d_in[0];   // [B,S,C]
    const int*   eidx = (const int*)d_in[1];     // [M,B]
    const float* dw   = (const float*)d_in[2];   // [M,N,C,D]
    const float* db   = (const float*)d_in[3];   // [M,N,D]
    const float* uw   = (const float*)d_in[4];   // [M,N,D,C]
    float*       out  = (float*)d_out;           // [M,B,S,C]

    bf16 *dwt, *uwt;
    cudaGetSymbolAddress((void**)&dwt, g_dwT);
    cudaGetSymbolAddress((void**)&uwt, g_uwT);

    cudaFuncSetAttribute(down_mma, cudaFuncAttributeMaxDynamicSharedMemorySize, SMEM_TOTAL);
    cudaFuncSetAttribute(up_mma,   cudaFuncAttributeMaxDynamicSharedMemorySize, SMEM_TOTAL);

    // preps
    x_split<<<(BB * SS * CD / 4) / 256, 256>>>(x);
    transpose_cvt<<<dim3(DD / 32, CD / 32, MR * NE), dim3(32, 8)>>>(dw, dwt, CD, DD);
    transpose_cvt<<<dim3(CD / 32, DD / 32, MR * NE), dim3(32, 8)>>>(uw, uwt, DD, CD);

    // GEMMs
    down_mma<<<dim3((SS / 128) * (DD / 128), BB, MR), 256, SMEM_TOTAL>>>(eidx, db);
    up_mma<<<dim3((SS / 128) * (CD / 128), BB, MR), 256, SMEM_TOTAL>>>(eidx, out);
}

// round 6
// speedup vs baseline: 1.1117x; 1.0068x over previous
#include <cuda_runtime.h>
#include <cuda_bf16.h>
#include <math.h>
#include <stdint.h>

#define MR 2
#define NE 8
#define CD 1024
#define DD 256
#define BB 32
#define SS 512
#define STAGES 3
// stage: Ah 8K | Al 8K | Bh 4K | Bl 4K = 24KB  (CTA tile 128m x 64n x 32k)
#define STAGE_BYTES 24576
#define OFF_AL 8192
#define OFF_BH 16384
#define OFF_BL 20480
#define SMEM_TOTAL (STAGES * STAGE_BYTES)   // 73728; 3 CTAs/SM = 216KB

typedef __nv_bfloat16 bf16;

// ---------------- static device scratch (combined hi|lo planes) --------------
// each logical row has 2*ld cols: hi plane at [0,ld), lo plane at [ld,2ld)
__device__ bf16 g_x[(size_t)BB * SS * 2 * CD];
__device__ bf16 g_z[(size_t)MR * BB * SS * 2 * DD];
__device__ bf16 g_dwT[(size_t)MR * NE * DD * 2 * CD];
__device__ bf16 g_uwT[(size_t)MR * NE * CD * 2 * DD];

// ---------------- ptx helpers ----------------
__device__ __forceinline__ uint32_t smem_u32(const void* p) {
    uint32_t a;
    asm("{ .reg .u64 t; cvta.to.shared.u64 t, %1; cvt.u32.u64 %0, t; }" : "=r"(a) : "l"(p));
    return a;
}
#define CP16(dst, src) \
    asm volatile("cp.async.cg.shared.global [%0], [%1], 16;" :: "r"(dst), "l"(src))
#define CP_COMMIT() asm volatile("cp.async.commit_group;")
#define CP_WAIT1()  asm volatile("cp.async.wait_group 1;")
#define CP_WAIT0()  asm volatile("cp.async.wait_group 0;")

#define LDSM4(r, a) \
    asm volatile("ldmatrix.sync.aligned.m8n8.x4.shared.b16 {%0,%1,%2,%3}, [%4];" \
        : "=r"((r)[0]), "=r"((r)[1]), "=r"((r)[2]), "=r"((r)[3]) : "r"(a))

#define MMA(d, a, b0, b1) \
    asm volatile("mma.sync.aligned.m16n8k16.row.col.f32.bf16.bf16.f32 " \
        "{%0,%1,%2,%3},{%4,%5,%6,%7},{%8,%9},{%0,%1,%2,%3};" \
        : "+f"((d)[0]), "+f"((d)[1]), "+f"((d)[2]), "+f"((d)[3]) \
        : "r"((a)[0]), "r"((a)[1]), "r"((a)[2]), "r"((a)[3]), "r"(b0), "r"(b1))

// XOR swizzle: rows are 64B (4 x 16B chunks); conflict-free ldmatrix
__device__ __forceinline__ uint32_t swz(uint32_t row, uint32_t chunk) {
    return row * 64u + ((chunk ^ ((row >> 1) & 3u)) << 4);
}
__device__ __forceinline__ uint32_t faddr(uint32_t stg, uint32_t region, int row, int ch) {
    return stg + region + (uint32_t)row * 64u +
           ((uint32_t)(ch ^ ((row >> 1) & 3)) << 4);
}

// ---------------- stage loader: 6x cp.async(16B) per thread ----------------
// A: 128 rows x 32k (2 chunks/thread/plane), B: 64 rows x 32k (1 chunk/thread/plane)
__device__ __forceinline__ void stage_load(uint32_t sbase,
                                           const bf16* __restrict__ A2, int lda,
                                           const bf16* __restrict__ B2, int ldb,
                                           int kc, int tid) {
    #pragma unroll
    for (int i = 0; i < 2; i++) {
        int q = tid + (i << 8);        // 512 chunks: 128 rows x 4 chunks
        int r = q >> 2, c = q & 3;
        uint32_t so = swz(r, c);
        const bf16* pa = A2 + (size_t)r * (2 * lda) + kc + c * 8;
        CP16(sbase + so,          pa);
        CP16(sbase + so + OFF_AL, pa + lda);
    }
    {
        int r = tid >> 2, c = tid & 3; // 256 chunks: 64 rows x 4 chunks
        uint32_t so = swz(r, c);
        const bf16* pb = B2 + (size_t)r * (2 * ldb) + kc + c * 8;
        CP16(sbase + so + OFF_BH, pb);
        CP16(sbase + so + OFF_BL, pb + ldb);
    }
}

// ---------------- GEMM mainloop: acc[2][4][4], warp tile 32x32 ----------------
__device__ __forceinline__ void gemm_main(uint32_t smem_b,
                                          const bf16* __restrict__ A2, int lda,
                                          const bf16* __restrict__ B2, int ldb,
                                          int nk, float acc[2][4][4], int tid) {
    const int lane = tid & 31, warp = tid >> 5;
    const int wm = (warp & 3) * 32, wn = (warp >> 2) * 32;
    const int r15 = lane & 15, chi = lane >> 4;
    const int wmr = wm + r15, wnr = wn + r15;

    stage_load(smem_b, A2, lda, B2, ldb, 0, tid);  CP_COMMIT();
    stage_load(smem_b + STAGE_BYTES, A2, lda, B2, ldb, 32, tid);  CP_COMMIT();

    for (int k = 0; k < nk; k++) {
        __syncthreads();   // S1: all reads of oldest stage done (overwrite safety)
        if (k + 2 < nk) {
            stage_load(smem_b + ((k + 2) % STAGES) * STAGE_BYTES,
                       A2, lda, B2, ldb, (k + 2) * 32, tid);
            CP_COMMIT();
            CP_WAIT1();
        } else {
            CP_WAIT0();
        }
        __syncthreads();   // S2: stage k visible to all threads

        uint32_t stg = smem_b + (k % STAGES) * STAGE_BYTES;
        #pragma unroll
        for (int ks = 0; ks < 2; ks++) {
            const int ch = ks * 2 + chi;
            uint32_t ah[2][4], al[2][4], bh[2][4], bl[2][4];
            // hi frags first; lo frags interleaved into pass1 (issue order = asm order)
            LDSM4(ah[0], faddr(stg, 0u,      wmr,      ch));
            LDSM4(ah[1], faddr(stg, 0u,      wmr + 16, ch));
            LDSM4(bh[0], faddr(stg, OFF_BH,  wnr,      ch));
            LDSM4(bh[1], faddr(stg, OFF_BH,  wnr + 16, ch));
            // pass1: ah*bh, prefetch al/bl
            #pragma unroll
            for (int mt = 0; mt < 2; mt++) {
                if (mt == 0) { LDSM4(al[0], faddr(stg, OFF_AL, wmr,      ch));
                               LDSM4(al[1], faddr(stg, OFF_AL, wmr + 16, ch)); }
                if (mt == 1) { LDSM4(bl[0], faddr(stg, OFF_BL, wnr,      ch));
                               LDSM4(bl[1], faddr(stg, OFF_BL, wnr + 16, ch)); }
                #pragma unroll
                for (int nt = 0; nt < 4; nt++)
                    MMA(acc[mt][nt], ah[mt], bh[nt >> 1][nt & 1], bh[nt >> 1][2 + (nt & 1)]);
            }
            // pass2: ah*bl
            #pragma unroll
            for (int mt = 0; mt < 2; mt++)
                #pragma unroll
                for (int nt = 0; nt < 4; nt++)
                    MMA(acc[mt][nt], ah[mt], bl[nt >> 1][nt & 1], bl[nt >> 1][2 + (nt & 1)]);
            // pass3: al*bh
            #pragma unroll
            for (int mt = 0; mt < 2; mt++)
                #pragma unroll
                for (int nt = 0; nt < 4; nt++)
                    MMA(acc[mt][nt], al[mt], bh[nt >> 1][nt & 1], bh[nt >> 1][2 + (nt & 1)]);
        }
    }
}

// ---------------- down: z = silu(x @ dw + db), z stored combined hi|lo --------
__global__ void __launch_bounds__(256, 3)
down_mma(const int* __restrict__ eidx, const float* __restrict__ db) {
    extern __shared__ char smem[];
    uint32_t smem_b = smem_u32(smem);
    const int tid = threadIdx.x, lane = tid & 31, warp = tid >> 5;
    const int wm = (warp & 3) * 32, wn = (warp >> 2) * 32;
    const int stile = blockIdx.x >> 2, ntile = blockIdx.x & 3;   // 4 stiles x 4 ntiles
    const int b = blockIdx.y, m = blockIdx.z;
    const int e = eidx[m * BB + b];

    const bf16* A2 = g_x   + ((size_t)b * SS + stile * 128) * (2 * CD);
    const bf16* B2 = g_dwT + ((size_t)(m * NE + e) * DD + ntile * 64) * (2 * CD);

    float acc[2][4][4];
    #pragma unroll
    for (int i = 0; i < 2; i++)
        #pragma unroll
        for (int j = 0; j < 4; j++)
            #pragma unroll
            for (int q = 0; q < 4; q++) acc[i][j][q] = 0.f;

    gemm_main(smem_b, A2, CD, B2, CD, CD / 32, acc, tid);

    const float* bias = db + (size_t)(m * NE + e) * DD;
    const size_t zrow0 = ((size_t)(m * BB + b) * SS + stile * 128);
    const int r0 = lane >> 2, cp = 2 * (lane & 3);

    #pragma unroll
    for (int mt = 0; mt < 2; mt++) {
        #pragma unroll
        for (int nt = 0; nt < 4; nt++) {
            const int col = ntile * 64 + wn + nt * 8 + cp;
            const float2 bv = *reinterpret_cast<const float2*>(bias + col);
            #pragma unroll
            for (int h = 0; h < 2; h++) {
                float v0 = acc[mt][nt][2 * h + 0] + bv.x;
                float v1 = acc[mt][nt][2 * h + 1] + bv.y;
                v0 = v0 / (1.f + __expf(-v0));
                v1 = v1 / (1.f + __expf(-v1));
                bf16 h0 = __float2bfloat16(v0), h1 = __float2bfloat16(v1);
                bf16 l0 = __float2bfloat16(v0 - __bfloat162float(h0));
                bf16 l1 = __float2bfloat16(v1 - __bfloat162float(h1));
                bf16* zb = g_z + (zrow0 + wm + mt * 16 + r0 + h * 8) * (2 * DD) + col;
                __nv_bfloat162 hp; hp.x = h0; hp.y = h1;
                __nv_bfloat162 lp; lp.x = l0; lp.y = l1;
                *reinterpret_cast<__nv_bfloat162*>(zb)      = hp;
                *reinterpret_cast<__nv_bfloat162*>(zb + DD) = lp;
            }
        }
    }
}

// ---------------- up: out = z @ uw (fp32 out) --------------------------------
__global__ void __launch_bounds__(256, 3)
up_mma(const int* __restrict__ eidx, float* __restrict__ out) {
    extern __shared__ char smem[];
    uint32_t smem_b = smem_u32(smem);
    const int tid = threadIdx.x, lane = tid & 31, warp = tid >> 5;
    const int wm = (warp & 3) * 32, wn = (warp >> 2) * 32;
    const int stile = blockIdx.x & 3, ctile = blockIdx.x >> 2;   // 4 stiles x 16 ctiles
    const int b = blockIdx.y, m = blockIdx.z;
    const int e = eidx[m * BB + b];

    const bf16* A2 = g_z   + ((size_t)(m * BB + b) * SS + stile * 128) * (2 * DD);
    const bf16* B2 = g_uwT + ((size_t)(m * NE + e) * CD + ctile * 64) * (2 * DD);

    float acc[2][4][4];
    #pragma unroll
    for (int i = 0; i < 2; i++)
        #pragma unroll
        for (int j = 0; j < 4; j++)
            #pragma unroll
            for (int q = 0; q < 4; q++) acc[i][j][q] = 0.f;

    gemm_main(smem_b, A2, DD, B2, DD, DD / 32, acc, tid);

    const size_t orow0 = ((size_t)(m * BB + b) * SS + stile * 128);
    const int r0 = lane >> 2, cp = 2 * (lane & 3);

    #pragma unroll
    for (int mt = 0; mt < 2; mt++) {
        #pragma unroll
        for (int nt = 0; nt < 4; nt++) {
            const int col = ctile * 64 + wn + nt * 8 + cp;
            #pragma unroll
            for (int h = 0; h < 2; h++) {
                const size_t off = (orow0 + wm + mt * 16 + r0 + h * 8) * CD + col;
                *reinterpret_cast<float2*>(out + off) =
                    make_float2(acc[mt][nt][2 * h + 0], acc[mt][nt][2 * h + 1]);
            }
        }
    }
}

// ---------------- prep: split x fp32 -> combined bf16 hi|lo ------------------
__global__ void __launch_bounds__(256)
x_split(const float* __restrict__ x) {
    size_t f = ((size_t)blockIdx.x * 256 + threadIdx.x) * 4;
    size_t row = f >> 10;            // / CD
    int c = (int)(f & (CD - 1));
    float4 v = *reinterpret_cast<const float4*>(x + f);
    float fv[4] = {v.x, v.y, v.z, v.w};
    __nv_bfloat162 hp[2], lp[2];
    #pragma unroll
    for (int j = 0; j < 2; j++) {
        bf16 h0 = __float2bfloat16(fv[2 * j]), h1 = __float2bfloat16(fv[2 * j + 1]);
        hp[j].x = h0; hp[j].y = h1;
        lp[j].x = __float2bfloat16(fv[2 * j] - __bfloat162float(h0));
        lp[j].y = __float2bfloat16(fv[2 * j + 1] - __bfloat162float(h1));
    }
    bf16* base = g_x + row * (2 * CD);
    *reinterpret_cast<uint2*>(base + c) =
        make_uint2(*reinterpret_cast<uint32_t*>(&hp[0]), *reinterpret_cast<uint32_t*>(&hp[1]));
    *reinterpret_cast<uint2*>(base + CD + c) =
        make_uint2(*reinterpret_cast<uint32_t*>(&lp[0]), *reinterpret_cast<uint32_t*>(&lp[1]));
}

// ---------------- prep: transpose [R x Cc] fp32 -> [Cc x 2R] combined bf16 ---
__global__ void transpose_cvt(const float* __restrict__ in,
                              bf16* __restrict__ outc, int R, int Cc) {
    __shared__ float t[32][33];
    const size_t mat = blockIdx.z;
    const float* src = in + mat * (size_t)R * Cc;
    bf16* dst = outc + mat * (size_t)Cc * 2 * R;
    int c0 = blockIdx.x * 32, r0 = blockIdx.y * 32;
    int tx = threadIdx.x;
    #pragma unroll
    for (int i = threadIdx.y; i < 32; i += 8)
        t[i][tx] = src[(size_t)(r0 + i) * Cc + c0 + tx];
    __syncthreads();
    #pragma unroll
    for (int i = threadIdx.y; i < 32; i += 8) {
        float v = t[tx][i];
        bf16 h = __float2bfloat16(v);
        size_t o = (size_t)(c0 + i) * 2 * R + r0 + tx;
        dst[o]     = h;
        dst[o + R] = __float2bfloat16(v - __bfloat162float(h));
    }
}

// ---------------- launch ------------------------------------------------------
extern "C" void kernel_launch(void* const* d_in, const int* in_sizes, int n_in,
                              void* d_out, int out_size) {
    const float* x    = (const float*)d_in[0];   // [B,S,C]
    const int*   eidx = (const int*)d_in[1];     // [M,B]
    const float* dw   = (const float*)d_in[2];   // [M,N,C,D]
    const float* db   = (const float*)d_in[3];   // [M,N,D]
    const float* uw   = (const float*)d_in[4];   // [M,N,D,C]
    float*       out  = (float*)d_out;           // [M,B,S,C]

    bf16 *dwt, *uwt;
    cudaGetSymbolAddress((void**)&dwt, g_dwT);
    cudaGetSymbolAddress((void**)&uwt, g_uwT);

    cudaFuncSetAttribute(down_mma, cudaFuncAttributeMaxDynamicSharedMemorySize, SMEM_TOTAL);
    cudaFuncSetAttribute(up_mma,   cudaFuncAttributeMaxDynamicSharedMemorySize, SMEM_TOTAL);

    // preps
    x_split<<<(BB * SS * CD / 4) / 256, 256>>>(x);
    transpose_cvt<<<dim3(DD / 32, CD / 32, MR * NE), dim3(32, 8)>>>(dw, dwt, CD, DD);
    transpose_cvt<<<dim3(CD / 32, DD / 32, MR * NE), dim3(32, 8)>>>(uw, uwt, DD, CD);

    // GEMMs: down grid = 4 stiles * 4 ntiles; up grid = 4 stiles * 16 ctiles
    down_mma<<<dim3(16, BB, MR), 256, SMEM_TOTAL>>>(eidx, db);
    up_mma<<<dim3(64, BB, MR), 256, SMEM_TOTAL>>>(eidx, out);
}

// round 7
// speedup vs baseline: 1.4704x; 1.3227x over previous
#include <cuda_runtime.h>
#include <cuda_fp16.h>
#include <math.h>
#include <stdint.h>

#define MR 2
#define NE 8
#define CD 1024
#define DD 256
#define BB 32
#define SS 512
#define STAGES 3
// stage: Ah 8K | Al 8K | B 4K = 20KB  (CTA tile 128m x 64n x 32k)
#define STAGE_BYTES 20480
#define OFF_AL 8192
#define OFF_B  16384
#define SMEM_TOTAL (STAGES * STAGE_BYTES)   // 61440; 3 CTAs/SM = 180KB

typedef __half fp16;

// ---------------- static device scratch (no allocs) ----------------
// x and z: combined hi|lo planes, row stride 2*ld (hi at [0,ld), lo at [ld,2ld))
__device__ fp16 g_x[(size_t)BB * SS * 2 * CD];
__device__ fp16 g_z[(size_t)MR * BB * SS * 2 * DD];
// weights: single fp16 plane, K-major
__device__ fp16 g_dwT[(size_t)MR * NE * DD * CD];
__device__ fp16 g_uwT[(size_t)MR * NE * CD * DD];

// ---------------- ptx helpers ----------------
__device__ __forceinline__ uint32_t smem_u32(const void* p) {
    uint32_t a;
    asm("{ .reg .u64 t; cvta.to.shared.u64 t, %1; cvt.u32.u64 %0, t; }" : "=r"(a) : "l"(p));
    return a;
}
#define CP16(dst, src) \
    asm volatile("cp.async.cg.shared.global [%0], [%1], 16;" :: "r"(dst), "l"(src))
#define CP_COMMIT() asm volatile("cp.async.commit_group;")
#define CP_WAIT1()  asm volatile("cp.async.wait_group 1;")
#define CP_WAIT0()  asm volatile("cp.async.wait_group 0;")

#define LDSM4(r, a) \
    asm volatile("ldmatrix.sync.aligned.m8n8.x4.shared.b16 {%0,%1,%2,%3}, [%4];" \
        : "=r"((r)[0]), "=r"((r)[1]), "=r"((r)[2]), "=r"((r)[3]) : "r"(a))

#define MMA(d, a, b0, b1) \
    asm volatile("mma.sync.aligned.m16n8k16.row.col.f32.f16.f16.f32 " \
        "{%0,%1,%2,%3},{%4,%5,%6,%7},{%8,%9},{%0,%1,%2,%3};" \
        : "+f"((d)[0]), "+f"((d)[1]), "+f"((d)[2]), "+f"((d)[3]) \
        : "r"((a)[0]), "r"((a)[1]), "r"((a)[2]), "r"((a)[3]), "r"(b0), "r"(b1))

// XOR swizzle: rows are 64B (4 x 16B chunks); conflict-free ldmatrix
__device__ __forceinline__ uint32_t swz(uint32_t row, uint32_t chunk) {
    return row * 64u + ((chunk ^ ((row >> 1) & 3u)) << 4);
}

// ---------------- stage loader: 5x cp.async(16B) per thread ----------------
__device__ __forceinline__ void stage_load(uint32_t sbase,
                                           const fp16* __restrict__ A2, int lda,
                                           const fp16* __restrict__ B1, int ldb,
                                           int kc, int tid) {
    #pragma unroll
    for (int i = 0; i < 2; i++) {
        int q = tid + (i << 8);        // 512 chunks: 128 rows x 4 chunks
        int r = q >> 2, c = q & 3;
        uint32_t so = swz(r, c);
        const fp16* pa = A2 + (size_t)r * (2 * lda) + kc + c * 8;
        CP16(sbase + so,          pa);
        CP16(sbase + so + OFF_AL, pa + lda);
    }
    {
        int r = tid >> 2, c = tid & 3; // 256 chunks: 64 rows x 4 chunks
        uint32_t so = swz(r, c);
        CP16(sbase + so + OFF_B, B1 + (size_t)r * ldb + kc + c * 8);
    }
}

// ---------------- GEMM mainloop: acc[2][4][4], warp tile 32x32, 2-term fp16 ---
__device__ __forceinline__ void gemm_main(uint32_t smem_b,
                                          const fp16* __restrict__ A2, int lda,
                                          const fp16* __restrict__ B1, int ldb,
                                          int nk, float acc[2][4][4], int tid) {
    const int lane = tid & 31, warp = tid >> 5;
    const int wm = (warp & 3) * 32, wn = (warp >> 2) * 32;
    const int r15 = lane & 15, chi = lane >> 4;
    const int wmr = wm + r15, wnr = wn + r15;

    // precomputed swizzled frag offsets (rows +16 share swizzle bits -> +1024)
    const uint32_t oa0 = swz(wmr, chi),     oa1 = swz(wmr, 2 + chi);
    const uint32_t ob0 = swz(wnr, chi) + OFF_B, ob1 = swz(wnr, 2 + chi) + OFF_B;

    stage_load(smem_b, A2, lda, B1, ldb, 0, tid);  CP_COMMIT();
    stage_load(smem_b + STAGE_BYTES, A2, lda, B1, ldb, 32, tid);  CP_COMMIT();

    uint32_t ah[2][4], al[2][4], bb[2][4];

    for (int k = 0; k < nk; k++) {
        if (k + 2 < nk) { CP_WAIT1(); } else { CP_WAIT0(); }
        __syncthreads();   // stage k visible; all reads of stage k-1 done
        if (k + 2 < nk) {
            stage_load(smem_b + ((k + 2) % STAGES) * STAGE_BYTES,
                       A2, lda, B1, ldb, (k + 2) * 32, tid);
            CP_COMMIT();
        }
        const uint32_t stg = smem_b + (k % STAGES) * STAGE_BYTES;

        // ---- ks0: load frags ----
        LDSM4(ah[0], stg + oa0);
        LDSM4(ah[1], stg + oa0 + 1024);
        LDSM4(al[0], stg + oa0 + OFF_AL);
        LDSM4(al[1], stg + oa0 + OFF_AL + 1024);
        LDSM4(bb[0], stg + ob0);
        LDSM4(bb[1], stg + ob0 + 1024);
        // pass1: ah*b
        #pragma unroll
        for (int mt = 0; mt < 2; mt++)
            #pragma unroll
            for (int nt = 0; nt < 4; nt++)
                MMA(acc[mt][nt], ah[mt], bb[nt >> 1][nt & 1], bb[nt >> 1][2 + (nt & 1)]);
        // pass2: al*b, interleave ks1 prefetch into dead registers
        LDSM4(ah[0], stg + oa1);              // ah dead after pass1
        LDSM4(ah[1], stg + oa1 + 1024);
        #pragma unroll
        for (int nt = 0; nt < 4; nt++)
            MMA(acc[0][nt], al[0], bb[nt >> 1][nt & 1], bb[nt >> 1][2 + (nt & 1)]);
        LDSM4(al[0], stg + oa1 + OFF_AL);     // al[0] dead
        #pragma unroll
        for (int nt = 0; nt < 4; nt++)
            MMA(acc[1][nt], al[1], bb[nt >> 1][nt & 1], bb[nt >> 1][2 + (nt & 1)]);
        // ---- ks1: remaining frags ----
        LDSM4(al[1], stg + oa1 + OFF_AL + 1024);
        LDSM4(bb[0], stg + ob1);
        LDSM4(bb[1], stg + ob1 + 1024);
        #pragma unroll
        for (int mt = 0; mt < 2; mt++)
            #pragma unroll
            for (int nt = 0; nt < 4; nt++)
                MMA(acc[mt][nt], ah[mt], bb[nt >> 1][nt & 1], bb[nt >> 1][2 + (nt & 1)]);
        #pragma unroll
        for (int mt = 0; mt < 2; mt++)
            #pragma unroll
            for (int nt = 0; nt < 4; nt++)
                MMA(acc[mt][nt], al[mt], bb[nt >> 1][nt & 1], bb[nt >> 1][2 + (nt & 1)]);
    }
}

// ---------------- down: z = silu(x @ dw + db), z stored combined hi|lo fp16 ---
__global__ void __launch_bounds__(256, 3)
down_mma(const int* __restrict__ eidx, const float* __restrict__ db) {
    extern __shared__ char smem[];
    uint32_t smem_b = smem_u32(smem);
    const int tid = threadIdx.x, lane = tid & 31, warp = tid >> 5;
    const int wm = (warp & 3) * 32, wn = (warp >> 2) * 32;
    const int stile = blockIdx.x >> 2, ntile = blockIdx.x & 3;
    const int b = blockIdx.y, m = blockIdx.z;
    const int e = eidx[m * BB + b];

    const fp16* A2 = g_x   + ((size_t)b * SS + stile * 128) * (2 * CD);
    const fp16* B1 = g_dwT + ((size_t)(m * NE + e) * DD + ntile * 64) * CD;

    float acc[2][4][4];
    #pragma unroll
    for (int i = 0; i < 2; i++)
        #pragma unroll
        for (int j = 0; j < 4; j++)
            #pragma unroll
            for (int q = 0; q < 4; q++) acc[i][j][q] = 0.f;

    gemm_main(smem_b, A2, CD, B1, CD, CD / 32, acc, tid);

    const float* bias = db + (size_t)(m * NE + e) * DD;
    const size_t zrow0 = ((size_t)(m * BB + b) * SS + stile * 128);
    const int r0 = lane >> 2, cp = 2 * (lane & 3);

    #pragma unroll
    for (int mt = 0; mt < 2; mt++) {
        #pragma unroll
        for (int nt = 0; nt < 4; nt++) {
            const int col = ntile * 64 + wn + nt * 8 + cp;
            const float2 bv = *reinterpret_cast<const float2*>(bias + col);
            #pragma unroll
            for (int h = 0; h < 2; h++) {
                float v0 = acc[mt][nt][2 * h + 0] + bv.x;
                float v1 = acc[mt][nt][2 * h + 1] + bv.y;
                v0 = v0 / (1.f + __expf(-v0));
                v1 = v1 / (1.f + __expf(-v1));
                fp16 h0 = __float2half(v0), h1 = __float2half(v1);
                fp16 l0 = __float2half(v0 - __half2float(h0));
                fp16 l1 = __float2half(v1 - __half2float(h1));
                fp16* zb = g_z + (zrow0 + wm + mt * 16 + r0 + h * 8) * (2 * DD) + col;
                __half2 hp; hp.x = h0; hp.y = h1;
                __half2 lp; lp.x = l0; lp.y = l1;
                *reinterpret_cast<__half2*>(zb)      = hp;
                *reinterpret_cast<__half2*>(zb + DD) = lp;
            }
        }
    }
}

// ---------------- up: out = z @ uw (fp32 out) --------------------------------
__global__ void __launch_bounds__(256, 3)
up_mma(const int* __restrict__ eidx, float* __restrict__ out) {
    extern __shared__ char smem[];
    uint32_t smem_b = smem_u32(smem);
    const int tid = threadIdx.x, lane = tid & 31, warp = tid >> 5;
    const int wm = (warp & 3) * 32, wn = (warp >> 2) * 32;
    const int stile = blockIdx.x & 3, ctile = blockIdx.x >> 2;
    const int b = blockIdx.y, m = blockIdx.z;
    const int e = eidx[m * BB + b];

    const fp16* A2 = g_z   + ((size_t)(m * BB + b) * SS + stile * 128) * (2 * DD);
    const fp16* B1 = g_uwT + ((size_t)(m * NE + e) * CD + ctile * 64) * DD;

    float acc[2][4][4];
    #pragma unroll
    for (int i = 0; i < 2; i++)
        #pragma unroll
        for (int j = 0; j < 4; j++)
            #pragma unroll
            for (int q = 0; q < 4; q++) acc[i][j][q] = 0.f;

    gemm_main(smem_b, A2, DD, B1, DD, DD / 32, acc, tid);

    const size_t orow0 = ((size_t)(m * BB + b) * SS + stile * 128);
    const int r0 = lane >> 2, cp = 2 * (lane & 3);

    #pragma unroll
    for (int mt = 0; mt < 2; mt++) {
        #pragma unroll
        for (int nt = 0; nt < 4; nt++) {
            const int col = ctile * 64 + wn + nt * 8 + cp;
            #pragma unroll
            for (int h = 0; h < 2; h++) {
                const size_t off = (orow0 + wm + mt * 16 + r0 + h * 8) * CD + col;
                *reinterpret_cast<float2*>(out + off) =
                    make_float2(acc[mt][nt][2 * h + 0], acc[mt][nt][2 * h + 1]);
            }
        }
    }
}

// ---------------- prep: split x fp32 -> combined fp16 hi|lo ------------------
__global__ void __launch_bounds__(256)
x_split(const float* __restrict__ x) {
    size_t f = ((size_t)blockIdx.x * 256 + threadIdx.x) * 4;
    size_t row = f >> 10;            // / CD
    int c = (int)(f & (CD - 1));
    float4 v = *reinterpret_cast<const float4*>(x + f);
    float fv[4] = {v.x, v.y, v.z, v.w};
    __half2 hp[2], lp[2];
    #pragma unroll
    for (int j = 0; j < 2; j++) {
        fp16 h0 = __float2half(fv[2 * j]), h1 = __float2half(fv[2 * j + 1]);
        hp[j].x = h0; hp[j].y = h1;
        lp[j].x = __float2half(fv[2 * j] - __half2float(h0));
        lp[j].y = __float2half(fv[2 * j + 1] - __half2float(h1));
    }
    fp16* base = g_x + row * (2 * CD);
    *reinterpret_cast<uint2*>(base + c) =
        make_uint2(*reinterpret_cast<uint32_t*>(&hp[0]), *reinterpret_cast<uint32_t*>(&hp[1]));
    *reinterpret_cast<uint2*>(base + CD + c) =
        make_uint2(*reinterpret_cast<uint32_t*>(&lp[0]), *reinterpret_cast<uint32_t*>(&lp[1]));
}

// ---------------- prep: transpose [R x Cc] fp32 -> [Cc x R] fp16 -------------
__global__ void transpose_cvt(const float* __restrict__ in,
                              fp16* __restrict__ outc, int R, int Cc) {
    __shared__ float t[32][33];
    const size_t mat = blockIdx.z;
    const float* src = in + mat * (size_t)R * Cc;
    fp16* dst = outc + mat * (size_t)Cc * R;
    int c0 = blockIdx.x * 32, r0 = blockIdx.y * 32;
    int tx = threadIdx.x;
    #pragma unroll
    for (int i = threadIdx.y; i < 32; i += 8)
        t[i][tx] = src[(size_t)(r0 + i) * Cc + c0 + tx];
    __syncthreads();
    #pragma unroll
    for (int i = threadIdx.y; i < 32; i += 8)
        dst[(size_t)(c0 + i) * R + r0 + tx] = __float2half(t[tx][i]);
}

// ---------------- launch ------------------------------------------------------
extern "C" void kernel_launch(void* const* d_in, const int* in_sizes, int n_in,
                              void* d_out, int out_size) {
    const float* x    = (const float*)d_in[0];   // [B,S,C]
    const int*   eidx = (const int*)d_in[1];     // [M,B]
    const float* dw   = (const float*)d_in[2];   // [M,N,C,D]
    const float* db   = (const float*)d_in[3];   // [M,N,D]
    const float* uw   = (const float*)d_in[4];   // [M,N,D,C]
    float*       out  = (float*)d_out;           // [M,B,S,C]

    fp16 *dwt, *uwt;
    cudaGetSymbolAddress((void**)&dwt, g_dwT);
    cudaGetSymbolAddress((void**)&uwt, g_uwT);

    cudaFuncSetAttribute(down_mma, cudaFuncAttributeMaxDynamicSharedMemorySize, SMEM_TOTAL);
    cudaFuncSetAttribute(up_mma,   cudaFuncAttributeMaxDynamicSharedMemorySize, SMEM_TOTAL);

    // preps
    x_split<<<(BB * SS * CD / 4) / 256, 256>>>(x);
    transpose_cvt<<<dim3(DD / 32, CD / 32, MR * NE), dim3(32, 8)>>>(dw, dwt, CD, DD);
    transpose_cvt<<<dim3(CD / 32, DD / 32, MR * NE), dim3(32, 8)>>>(uw, uwt, DD, CD);

    // GEMMs
    down_mma<<<dim3(16, BB, MR), 256, SMEM_TOTAL>>>(eidx, db);
    up_mma<<<dim3(64, BB, MR), 256, SMEM_TOTAL>>>(eidx, out);
}

// round 8
// speedup vs baseline: 2.1080x; 1.4336x over previous
#include <cuda_runtime.h>
#include <cuda_fp16.h>
#include <math.h>
#include <stdint.h>

#define MR 2
#define NE 8
#define CD 1024
#define DD 256
#define BB 32
#define SS 512
#define STAGES 4
// stage: A 8K | B 8K = 16KB  (CTA tile 128m x 128n x 32k, fp16 single term)
#define STAGE_BYTES 16384
#define OFF_B  8192
#define SMEM_TOTAL (STAGES * STAGE_BYTES)   // 65536; 2 CTAs/SM = 128KB

typedef __half fp16;

// ---------------- static device scratch (no allocs) ----------------
__device__ fp16 g_x[(size_t)BB * SS * CD];        // x as fp16, K-major (C contig)
__device__ fp16 g_z[(size_t)MR * BB * SS * DD];   // z as fp16, K-major (D contig)
__device__ fp16 g_dwT[(size_t)MR * NE * DD * CD]; // [D][C]
__device__ fp16 g_uwT[(size_t)MR * NE * CD * DD]; // [C][D]

// ---------------- ptx helpers ----------------
__device__ __forceinline__ uint32_t smem_u32(const void* p) {
    uint32_t a;
    asm("{ .reg .u64 t; cvta.to.shared.u64 t, %1; cvt.u32.u64 %0, t; }" : "=r"(a) : "l"(p));
    return a;
}
#define CP16(dst, src) \
    asm volatile("cp.async.cg.shared.global [%0], [%1], 16;" :: "r"(dst), "l"(src))
#define CP_COMMIT() asm volatile("cp.async.commit_group;")
#define CP_WAIT2()  asm volatile("cp.async.wait_group 2;")
#define CP_WAIT1()  asm volatile("cp.async.wait_group 1;")
#define CP_WAIT0()  asm volatile("cp.async.wait_group 0;")

#define LDSM4(r, a) \
    asm volatile("ldmatrix.sync.aligned.m8n8.x4.shared.b16 {%0,%1,%2,%3}, [%4];" \
        : "=r"((r)[0]), "=r"((r)[1]), "=r"((r)[2]), "=r"((r)[3]) : "r"(a))

#define MMA(d, a, b0, b1) \
    asm volatile("mma.sync.aligned.m16n8k16.row.col.f32.f16.f16.f32 " \
        "{%0,%1,%2,%3},{%4,%5,%6,%7},{%8,%9},{%0,%1,%2,%3};" \
        : "+f"((d)[0]), "+f"((d)[1]), "+f"((d)[2]), "+f"((d)[3]) \
        : "r"((a)[0]), "r"((a)[1]), "r"((a)[2]), "r"((a)[3]), "r"(b0), "r"(b1))

// XOR swizzle: rows are 64B (4 x 16B chunks); conflict-free ldmatrix
__device__ __forceinline__ uint32_t swz(uint32_t row, uint32_t chunk) {
    return row * 64u + ((chunk ^ ((row >> 1) & 3u)) << 4);
}

// ---------------- stage loader: 4x cp.async(16B) per thread ----------------
// A: 128 rows x 32k, B: 128 rows x 32k; 512 chunks each over 256 threads
__device__ __forceinline__ void stage_load(uint32_t sbase,
                                           const fp16* __restrict__ A1, int lda,
                                           const fp16* __restrict__ B1, int ldb,
                                           int kc, int tid) {
    #pragma unroll
    for (int i = 0; i < 2; i++) {
        int q = tid + (i << 8);
        int r = q >> 2, c = q & 3;
        uint32_t so = swz(r, c);
        CP16(sbase + so,         A1 + (size_t)r * lda + kc + c * 8);
        CP16(sbase + so + OFF_B, B1 + (size_t)r * ldb + kc + c * 8);
    }
}

// ---------------- GEMM mainloop: warp tile 64x32, acc[4][4][4] ----------------
__device__ __forceinline__ void gemm_main(uint32_t smem_b,
                                          const fp16* __restrict__ A1, int lda,
                                          const fp16* __restrict__ B1, int ldb,
                                          int nk, float acc[4][4][4], int tid) {
    const int lane = tid & 31, warp = tid >> 5;
    const int wm = (warp & 1) * 64, wn = (warp >> 1) * 32;
    const int r15 = lane & 15, chi = lane >> 4;

    // per-lane swizzled frag offsets; ks1 chunk = chi^2 -> address XOR 32;
    // rows +16 share swizzle bits -> +1024
    const uint32_t a0 = swz((uint32_t)(wm + r15), (uint32_t)chi);
    const uint32_t b0 = swz((uint32_t)(wn + r15), (uint32_t)chi) + OFF_B;

    stage_load(smem_b,                   A1, lda, B1, ldb, 0,  tid);  CP_COMMIT();
    stage_load(smem_b + STAGE_BYTES,     A1, lda, B1, ldb, 32, tid);  CP_COMMIT();
    stage_load(smem_b + 2 * STAGE_BYTES, A1, lda, B1, ldb, 64, tid);  CP_COMMIT();

    uint32_t ah[4][4], bb[2][4];

    for (int k = 0; k < nk; k++) {
        if (k + 3 <= nk)      { CP_WAIT2(); }
        else if (k + 2 <= nk) { CP_WAIT1(); }
        else                  { CP_WAIT0(); }
        __syncthreads();   // stage k visible to all; reads of stage k-1 done
        if (k + 3 < nk) {
            stage_load(smem_b + ((k + 3) & 3) * STAGE_BYTES,
                       A1, lda, B1, ldb, (k + 3) * 32, tid);
            CP_COMMIT();
        }
        const uint32_t stg = smem_b + ((k & 3) << 14);

        #pragma unroll
        for (int ks = 0; ks < 2; ks++) {
            const uint32_t ax = stg + (ks ? (a0 ^ 32u) : a0);
            const uint32_t bx = stg + (ks ? (b0 ^ 32u) : b0);
            LDSM4(bb[0], bx);
            LDSM4(bb[1], bx + 1024);
            LDSM4(ah[0], ax);
            LDSM4(ah[1], ax + 1024);
            LDSM4(ah[2], ax + 2048);
            LDSM4(ah[3], ax + 3072);
            #pragma unroll
            for (int mt = 0; mt < 4; mt++)
                #pragma unroll
                for (int nt = 0; nt < 4; nt++)
                    MMA(acc[mt][nt], ah[mt], bb[nt >> 1][nt & 1], bb[nt >> 1][2 + (nt & 1)]);
        }
    }
}

// ---------------- down: z = silu(x @ dw + db), fp16 z -------------------------
__global__ void __launch_bounds__(256, 2)
down_mma(const int* __restrict__ eidx, const float* __restrict__ db) {
    extern __shared__ char smem[];
    uint32_t smem_b = smem_u32(smem);
    const int tid = threadIdx.x, lane = tid & 31, warp = tid >> 5;
    const int wm = (warp & 1) * 64, wn = (warp >> 1) * 32;
    const int stile = blockIdx.x >> 1, ntile = blockIdx.x & 1;
    const int b = blockIdx.y, m = blockIdx.z;
    const int e = eidx[m * BB + b];

    const fp16* A1 = g_x   + ((size_t)b * SS + stile * 128) * CD;
    const fp16* B1 = g_dwT + ((size_t)(m * NE + e) * DD + ntile * 128) * CD;

    float acc[4][4][4];
    #pragma unroll
    for (int i = 0; i < 4; i++)
        #pragma unroll
        for (int j = 0; j < 4; j++)
            #pragma unroll
            for (int q = 0; q < 4; q++) acc[i][j][q] = 0.f;

    gemm_main(smem_b, A1, CD, B1, CD, CD / 32, acc, tid);

    const float* bias = db + (size_t)(m * NE + e) * DD;
    const size_t zrow0 = ((size_t)(m * BB + b) * SS + stile * 128);
    const int r0 = lane >> 2, cp = 2 * (lane & 3);

    #pragma unroll
    for (int mt = 0; mt < 4; mt++) {
        #pragma unroll
        for (int nt = 0; nt < 4; nt++) {
            const int col = ntile * 128 + wn + nt * 8 + cp;
            const float2 bv = *reinterpret_cast<const float2*>(bias + col);
            #pragma unroll
            for (int h = 0; h < 2; h++) {
                float v0 = acc[mt][nt][2 * h + 0] + bv.x;
                float v1 = acc[mt][nt][2 * h + 1] + bv.y;
                v0 = v0 / (1.f + __expf(-v0));
                v1 = v1 / (1.f + __expf(-v1));
                __half2 hp; hp.x = __float2half(v0); hp.y = __float2half(v1);
                *reinterpret_cast<__half2*>(
                    g_z + (zrow0 + wm + mt * 16 + r0 + h * 8) * DD + col) = hp;
            }
        }
    }
}

// ---------------- up: out = z @ uw (fp32 out) --------------------------------
__global__ void __launch_bounds__(256, 2)
up_mma(const int* __restrict__ eidx, float* __restrict__ out) {
    extern __shared__ char smem[];
    uint32_t smem_b = smem_u32(smem);
    const int tid = threadIdx.x, lane = tid & 31, warp = tid >> 5;
    const int wm = (warp & 1) * 64, wn = (warp >> 1) * 32;
    const int stile = blockIdx.x & 3, ctile = blockIdx.x >> 2;
    const int b = blockIdx.y, m = blockIdx.z;
    const int e = eidx[m * BB + b];

    const fp16* A1 = g_z   + ((size_t)(m * BB + b) * SS + stile * 128) * DD;
    const fp16* B1 = g_uwT + ((size_t)(m * NE + e) * CD + ctile * 128) * DD;

    float acc[4][4][4];
    #pragma unroll
    for (int i = 0; i < 4; i++)
        #pragma unroll
        for (int j = 0; j < 4; j++)
            #pragma unroll
            for (int q = 0; q < 4; q++) acc[i][j][q] = 0.f;

    gemm_main(smem_b, A1, DD, B1, DD, DD / 32, acc, tid);

    const size_t orow0 = ((size_t)(m * BB + b) * SS + stile * 128);
    const int r0 = lane >> 2, cp = 2 * (lane & 3);

    #pragma unroll
    for (int mt = 0; mt < 4; mt++) {
        #pragma unroll
        for (int nt = 0; nt < 4; nt++) {
            const int col = ctile * 128 + wn + nt * 8 + cp;
            #pragma unroll
            for (int h = 0; h < 2; h++) {
                const size_t off = (orow0 + wm + mt * 16 + r0 + h * 8) * CD + col;
                *reinterpret_cast<float2*>(out + off) =
                    make_float2(acc[mt][nt][2 * h + 0], acc[mt][nt][2 * h + 1]);
            }
        }
    }
}

// ---------------- prep: x fp32 -> fp16 ----------------------------------------
__global__ void __launch_bounds__(256)
x_cvt(const float* __restrict__ x) {
    size_t i = ((size_t)blockIdx.x * 256 + threadIdx.x) * 4;
    float4 v = *reinterpret_cast<const float4*>(x + i);
    __half2 p0, p1;
    p0.x = __float2half(v.x); p0.y = __float2half(v.y);
    p1.x = __float2half(v.z); p1.y = __float2half(v.w);
    *reinterpret_cast<uint2*>(g_x + i) =
        make_uint2(*reinterpret_cast<uint32_t*>(&p0), *reinterpret_cast<uint32_t*>(&p1));
}

// ---------------- prep: transpose [R x Cc] fp32 -> [Cc x R] fp16 -------------
__global__ void transpose_cvt(const float* __restrict__ in,
                              fp16* __restrict__ outc, int R, int Cc) {
    __shared__ float t[32][33];
    const size_t mat = blockIdx.z;
    const float* src = in + mat * (size_t)R * Cc;
    fp16* dst = outc + mat * (size_t)Cc * R;
    int c0 = blockIdx.x * 32, r0 = blockIdx.y * 32;
    int tx = threadIdx.x;
    #pragma unroll
    for (int i = threadIdx.y; i < 32; i += 8)
        t[i][tx] = src[(size_t)(r0 + i) * Cc + c0 + tx];
    __syncthreads();
    #pragma unroll
    for (int i = threadIdx.y; i < 32; i += 8)
        dst[(size_t)(c0 + i) * R + r0 + tx] = __float2half(t[tx][i]);
}

// ---------------- launch ------------------------------------------------------
extern "C" void kernel_launch(void* const* d_in, const int* in_sizes, int n_in,
                              void* d_out, int out_size) {
    const float* x    = (const float*)d_in[0];   // [B,S,C]
    const int*   eidx = (const int*)d_in[1];     // [M,B]
    const float* dw   = (const float*)d_in[2];   // [M,N,C,D]
    const float* db   = (const float*)d_in[3];   // [M,N,D]
    const float* uw   = (const float*)d_in[4];   // [M,N,D,C]
    float*       out  = (float*)d_out;           // [M,B,S,C]

    fp16 *dwt, *uwt;
    cudaGetSymbolAddress((void**)&dwt, g_dwT);
    cudaGetSymbolAddress((void**)&uwt, g_uwT);

    cudaFuncSetAttribute(down_mma, cudaFuncAttributeMaxDynamicSharedMemorySize, SMEM_TOTAL);
    cudaFuncSetAttribute(up_mma,   cudaFuncAttributeMaxDynamicSharedMemorySize, SMEM_TOTAL);

    // preps
    x_cvt<<<(BB * SS * CD / 4) / 256, 256>>>(x);
    transpose_cvt<<<dim3(DD / 32, CD / 32, MR * NE), dim3(32, 8)>>>(dw, dwt, CD, DD);
    transpose_cvt<<<dim3(CD / 32, DD / 32, MR * NE), dim3(32, 8)>>>(uw, uwt, DD, CD);

    // GEMMs: down grid = 4 stiles * 2 ntiles; up grid = 4 stiles * 8 ctiles
    down_mma<<<dim3(8, BB, MR), 256, SMEM_TOTAL>>>(eidx, db);
    up_mma<<<dim3(32, BB, MR), 256, SMEM_TOTAL>>>(eidx, out);
}